// round 11
// baseline (speedup 1.0000x reference)
#include <cuda_runtime.h>
#include <cuda_bf16.h>
#include <cstdint>

#define BB 16
#define TT 2048
#define DD 512
#define AA 64
#define NROWS (BB*TT)

// ---------------- device scratch ----------------
__device__ __align__(16) __nv_bfloat16 g_Qhi[NROWS*AA];
__device__ __align__(16) __nv_bfloat16 g_Qlo[NROWS*AA];
__device__ __align__(16) __nv_bfloat16 g_Khi[NROWS*AA];
__device__ __align__(16) __nv_bfloat16 g_Klo[NROWS*AA];
__device__ __align__(16) __nv_bfloat16 g_WThi[128*DD];  // [n][k], n: 0..63 Q, 64..127 K
__device__ __align__(16) __nv_bfloat16 g_WTlo[128*DD];
__device__ __align__(16) float2 g_wz[NROWS];  // (q_mask*vsum, kz) per key row
__device__ __align__(16) float g_l[NROWS];    // softmax denominator partials
__device__ __align__(16) float g_acc[NROWS];  // softmax numerator partials
__device__ float g_wqs[DD], g_wks[DD], g_wvs[DD];
__device__ float g_bs[3];

#define SC2F 0.18033688011112043f   // 0.125 * log2(e)

// ---------------- helpers ----------------
__device__ __forceinline__ uint32_t smem_u32(const void* p) {
    return (uint32_t)__cvta_generic_to_shared(p);
}
__device__ __forceinline__ float ex2f(float x) {
    float y; asm("ex2.approx.ftz.f32 %0, %1;" : "=f"(y) : "f"(x)); return y;
}
__device__ __forceinline__ void ldsm4(uint32_t* r, uint32_t addr) {
    asm volatile("ldmatrix.sync.aligned.m8n8.x4.shared.b16 {%0,%1,%2,%3}, [%4];"
        : "=r"(r[0]), "=r"(r[1]), "=r"(r[2]), "=r"(r[3]) : "r"(addr));
}
__device__ __forceinline__ void mma16816(float* c, const uint32_t* a, const uint32_t* b) {
    asm volatile("mma.sync.aligned.m16n8k16.row.col.f32.bf16.bf16.f32 "
        "{%0,%1,%2,%3}, {%4,%5,%6,%7}, {%8,%9}, {%0,%1,%2,%3};"
        : "+f"(c[0]), "+f"(c[1]), "+f"(c[2]), "+f"(c[3])
        : "r"(a[0]), "r"(a[1]), "r"(a[2]), "r"(a[3]), "r"(b[0]), "r"(b[1]));
}
#define CPA(dst, src) asm volatile("cp.async.cg.shared.global [%0], [%1], 16;" :: "r"(dst), "l"(src))
#define CPC() asm volatile("cp.async.commit_group;" ::: "memory")
#define CPW0() asm volatile("cp.async.wait_group 0;" ::: "memory")
#define CPW1() asm volatile("cp.async.wait_group 1;" ::: "memory")

// 128-byte rows, xor swizzle (bits 4-6) for conflict-free ldmatrix
__device__ __forceinline__ uint32_t tadr(uint32_t base, int r, int kb) {
    return base + ((((uint32_t)r << 7) | (uint32_t)kb) ^ (((uint32_t)(r & 7)) << 4));
}
__device__ __forceinline__ uint32_t pk2(__nv_bfloat16 a, __nv_bfloat16 b) {
    __nv_bfloat162 t = __halves2bfloat162(a, b);
    return *reinterpret_cast<uint32_t*>(&t);
}
__device__ __forceinline__ uint32_t pkf(float a, float b) {
    __nv_bfloat162 t = __floats2bfloat162_rn(a, b);
    return *reinterpret_cast<uint32_t*>(&t);
}

// ---------------- kernel A: zero out + l/acc partials ----------------
__global__ __launch_bounds__(512) void k_zero(float* __restrict__ out) {
    int idx = blockIdx.x * 512 + threadIdx.x;   // grid 64 -> 32768 threads
    g_l[idx] = 0.f;
    g_acc[idx] = 0.f;
    if (blockIdx.x < 16) out[blockIdx.x * 512 + threadIdx.x] = 0.f;
}

// ---------------- kernel 0: W col sums + transpose, parallel (warp per d) ----------------
__global__ __launch_bounds__(256) void k_wsum(const float* __restrict__ Wq, const float* __restrict__ Wk,
                       const float* __restrict__ Wv,
                       const float* __restrict__ bq, const float* __restrict__ bk,
                       const float* __restrict__ bv) {
    int wid = threadIdx.x >> 5, lane = threadIdx.x & 31;
    int d = blockIdx.x * 8 + wid;

    float wq0 = Wq[d*AA + lane],      wq1 = Wq[d*AA + 32 + lane];
    float wk0 = Wk[d*AA + lane],      wk1 = Wk[d*AA + 32 + lane];
    float wv0 = Wv[d*AA + lane],      wv1 = Wv[d*AA + 32 + lane];

    float sq = wq0 + wq1, sk = wk0 + wk1, sv = wv0 + wv1;
    #pragma unroll
    for (int off = 16; off > 0; off >>= 1) {
        sq += __shfl_xor_sync(0xffffffffu, sq, off);
        sk += __shfl_xor_sync(0xffffffffu, sk, off);
        sv += __shfl_xor_sync(0xffffffffu, sv, off);
    }
    if (lane == 0) { g_wqs[d] = sq; g_wks[d] = sk; g_wvs[d] = sv; }

    #pragma unroll
    for (int half = 0; half < 2; half++) {
        int a = lane + half * 32;
        float vq = half ? wq1 : wq0;
        float vk = half ? wk1 : wk0;
        __nv_bfloat16 hq = __float2bfloat16_rn(vq);
        __nv_bfloat16 hk = __float2bfloat16_rn(vk);
        g_WThi[a*DD + d]        = hq;
        g_WTlo[a*DD + d]        = __float2bfloat16_rn(vq - __bfloat162float(hq));
        g_WThi[(64 + a)*DD + d] = hk;
        g_WTlo[(64 + a)*DD + d] = __float2bfloat16_rn(vk - __bfloat162float(hk));
    }

    if (blockIdx.x == 0 && threadIdx.x < 3) {
        const float* bb = (threadIdx.x == 0) ? bq : (threadIdx.x == 1) ? bk : bv;
        float s = 0.f;
        #pragma unroll 8
        for (int a = 0; a < AA; a++) s += bb[a];
        g_bs[threadIdx.x] = s;
    }
}

// ---------------- kernel 1: HMMA Q,K projection + fused mask rowsums ----------------
#define PJ_A 0                    // 2 bufs x 8K (64 rows x 128B)
#define PJ_B 16384                // 2 bufs x 16K (128 n x 128B)
#define PJ_SMEM (16384 + 32768)

__global__ __launch_bounds__(256) void k_proj_mma(const float* __restrict__ inp,
                                                  const float* __restrict__ bq,
                                                  const float* __restrict__ bk) {
    extern __shared__ char sm[];
    uint32_t smb = smem_u32(sm);
    int tid = threadIdx.x;
    int lane = tid & 31;
    int wid = tid >> 5;
    int m0 = (wid >> 2) * 32;
    int wn = wid & 3;
    int n0 = wn * 32;
    int rowbase = blockIdx.x * 64;

    int ar = tid >> 2, aq = tid & 3;
    int bn = tid >> 1, bh = tid & 1;

    float C[2][4][4];
    #pragma unroll
    for (int a = 0; a < 2; a++)
        #pragma unroll
        for (int b = 0; b < 4; b++)
            #pragma unroll
            for (int c = 0; c < 4; c++) C[a][b][c] = 0.f;
    float dq = 0.f, dk = 0.f, dv = 0.f;

    const float* arow_p = inp + (size_t)(rowbase + ar) * DD + aq * 8;
    const char* bsrc_h = (const char*)g_WThi + (size_t)bn * 1024 + bh * 32;
    const char* bsrc_l = (const char*)g_WTlo + (size_t)bn * 1024 + bh * 32;

    float4 xa = *(const float4*)(arow_p);
    float4 xb = *(const float4*)(arow_p + 4);
    {
        uint32_t bb = smb + PJ_B;
        CPA(tadr(bb, bn, bh*32),           bsrc_h);
        CPA(tadr(bb, bn, bh*32 + 16),      bsrc_h + 16);
        CPA(tadr(bb, bn, 64 + bh*32),      bsrc_l);
        CPA(tadr(bb, bn, 64 + bh*32 + 16), bsrc_l + 16);
        CPC();
    }

    for (int kc = 0; kc < 16; kc++) {
        int buf = kc & 1;
        {
            int koff = kc * 32 + aq * 8;
            const float4* wq4 = (const float4*)(g_wqs + koff);
            const float4* wk4 = (const float4*)(g_wks + koff);
            const float4* wv4 = (const float4*)(g_wvs + koff);
            float4 a0 = wq4[0], a1 = wq4[1];
            dq += xa.x*a0.x + xa.y*a0.y + xa.z*a0.z + xa.w*a0.w
                + xb.x*a1.x + xb.y*a1.y + xb.z*a1.z + xb.w*a1.w;
            float4 b0 = wk4[0], b1 = wk4[1];
            dk += xa.x*b0.x + xa.y*b0.y + xa.z*b0.z + xa.w*b0.w
                + xb.x*b1.x + xb.y*b1.y + xb.z*b1.z + xb.w*b1.w;
            float4 c0 = wv4[0], c1 = wv4[1];
            dv += xa.x*c0.x + xa.y*c0.y + xa.z*c0.z + xa.w*c0.w
                + xb.x*c1.x + xb.y*c1.y + xb.z*c1.z + xb.w*c1.w;
        }
        {
            __nv_bfloat16 h0 = __float2bfloat16_rn(xa.x), h1 = __float2bfloat16_rn(xa.y);
            __nv_bfloat16 h2 = __float2bfloat16_rn(xa.z), h3 = __float2bfloat16_rn(xa.w);
            __nv_bfloat16 h4 = __float2bfloat16_rn(xb.x), h5 = __float2bfloat16_rn(xb.y);
            __nv_bfloat16 h6 = __float2bfloat16_rn(xb.z), h7 = __float2bfloat16_rn(xb.w);
            uint4 hw, lw;
            hw.x = pk2(h0, h1); hw.y = pk2(h2, h3); hw.z = pk2(h4, h5); hw.w = pk2(h6, h7);
            lw.x = pkf(xa.x - __bfloat162float(h0), xa.y - __bfloat162float(h1));
            lw.y = pkf(xa.z - __bfloat162float(h2), xa.w - __bfloat162float(h3));
            lw.z = pkf(xb.x - __bfloat162float(h4), xb.y - __bfloat162float(h5));
            lw.w = pkf(xb.z - __bfloat162float(h6), xb.w - __bfloat162float(h7));
            uint32_t abase = PJ_A + buf * 8192;
            *(uint4*)(sm + tadr(abase, ar, aq*16))      = hw;
            *(uint4*)(sm + tadr(abase, ar, 64 + aq*16)) = lw;
        }
        if (kc < 15) {
            xa = *(const float4*)(arow_p + (kc + 1) * 32);
            xb = *(const float4*)(arow_p + (kc + 1) * 32 + 4);
        }
        if (kc < 15) {
            uint32_t bb = smb + PJ_B + (buf ^ 1) * 16384;
            const char* bh_p = bsrc_h + (kc + 1) * 64;
            const char* bl_p = bsrc_l + (kc + 1) * 64;
            CPA(tadr(bb, bn, bh*32),           bh_p);
            CPA(tadr(bb, bn, bh*32 + 16),      bh_p + 16);
            CPA(tadr(bb, bn, 64 + bh*32),      bl_p);
            CPA(tadr(bb, bn, 64 + bh*32 + 16), bl_p + 16);
            CPC();
            CPW1();
        } else {
            CPW0();
        }
        __syncthreads();

        uint32_t Ab = smb + PJ_A + buf * 8192;
        uint32_t Bb = smb + PJ_B + buf * 16384;
        #pragma unroll
        for (int ks = 0; ks < 2; ks++) {
            int akb = ks*32 + ((lane >> 4) << 4);
            int arw = m0 + (lane & 15);
            uint32_t ahi[2][4], alo[2][4];
            ldsm4(ahi[0], tadr(Ab, arw,      akb));
            ldsm4(ahi[1], tadr(Ab, arw + 16, akb));
            ldsm4(alo[0], tadr(Ab, arw,      akb + 64));
            ldsm4(alo[1], tadr(Ab, arw + 16, akb + 64));
            int brow = (lane & 7) | ((lane >> 4) << 3);
            int bkb = ks*32 + ((lane & 8) << 1);
            uint32_t bhi[4][2], blo[4][2];
            ldsm4(&bhi[0][0], tadr(Bb, n0 + brow,      bkb));
            ldsm4(&bhi[2][0], tadr(Bb, n0 + 16 + brow, bkb));
            ldsm4(&blo[0][0], tadr(Bb, n0 + brow,      bkb + 64));
            ldsm4(&blo[2][0], tadr(Bb, n0 + 16 + brow, bkb + 64));
            #pragma unroll
            for (int mf = 0; mf < 2; mf++)
                #pragma unroll
                for (int nf = 0; nf < 4; nf++) {
                    mma16816(C[mf][nf], ahi[mf], bhi[nf]);
                    mma16816(C[mf][nf], ahi[mf], blo[nf]);
                    mma16816(C[mf][nf], alo[mf], bhi[nf]);
                }
        }
    }

    // ---- finalize mask rowsums ----
    dq += __shfl_xor_sync(0xffffffffu, dq, 1);
    dq += __shfl_xor_sync(0xffffffffu, dq, 2);
    dk += __shfl_xor_sync(0xffffffffu, dk, 1);
    dk += __shfl_xor_sync(0xffffffffu, dk, 2);
    dv += __shfl_xor_sync(0xffffffffu, dv, 1);
    dv += __shfl_xor_sync(0xffffffffu, dv, 2);
    if (aq == 0) {
        float qs = dq + g_bs[0];
        float ks_ = dk + g_bs[1];
        float vs = dv + g_bs[2];
        g_wz[rowbase + ar] = make_float2((qs != 0.f) ? vs : 0.f,
                                         (ks_ == 0.f) ? 1.f : 0.f);
    }

    // ---- epilogue ----
    __nv_bfloat16* dsthi; __nv_bfloat16* dstlo; const float* bias; int nb; float scl;
    if (wn < 2) { dsthi = g_Qhi; dstlo = g_Qlo; bias = bq; nb = wn * 32; scl = SC2F; }
    else        { dsthi = g_Khi; dstlo = g_Klo; bias = bk; nb = (wn - 2) * 32; scl = 1.0f; }
    #pragma unroll
    for (int mf = 0; mf < 2; mf++) {
        int r0 = rowbase + m0 + mf*16 + (lane >> 2);
        #pragma unroll
        for (int nf = 0; nf < 4; nf++) {
            int c = nb + nf*8 + (lane & 3)*2;
            float b0 = __ldg(bias + c), b1 = __ldg(bias + c + 1);
            float v0 = (C[mf][nf][0] + b0) * scl, v1 = (C[mf][nf][1] + b1) * scl;
            float v2 = (C[mf][nf][2] + b0) * scl, v3 = (C[mf][nf][3] + b1) * scl;
            __nv_bfloat16 h0 = __float2bfloat16_rn(v0), h1 = __float2bfloat16_rn(v1);
            __nv_bfloat16 h2 = __float2bfloat16_rn(v2), h3 = __float2bfloat16_rn(v3);
            *(uint32_t*)(dsthi + (size_t)r0*AA + c) = pk2(h0, h1);
            *(uint32_t*)(dstlo + (size_t)r0*AA + c) = pkf(v0 - __bfloat162float(h0), v1 - __bfloat162float(h1));
            *(uint32_t*)(dsthi + (size_t)(r0+8)*AA + c) = pk2(h2, h3);
            *(uint32_t*)(dstlo + (size_t)(r0+8)*AA + c) = pkf(v2 - __bfloat162float(h2), v3 - __bfloat162float(h3));
        }
    }
}

// ---------------- kernel 2: HMMA flash attention, 3-way split accumulators ----------------
// grid (16 q-tiles, BB, 4 kv-splits); CTA 128 thr; 128q/CTA, 32q/warp; 8 key tiles of 64.
// Per nfp: 3 independent accumulator groups (hi*hi, hi*lo, lo*hi) -> chain depth 4 not 12.
#define AT_QHI 0                   // 16K (128 rows x 128B)
#define AT_QLO 16384               // 16K
#define AT_K   32768               // 2 bufs x (hi 8K | lo 8K)
#define AT_WS  65536               // 2 x 512B (float2 per key)
#define AT_SMEM (65536 + 1024)
#define NKT_SPLIT 8

__global__ __launch_bounds__(128, 2) void k_attn_mma() {
    extern __shared__ char sm[];
    uint32_t smb = smem_u32(sm);
    int tid = threadIdx.x;
    int lane = tid & 31;
    int wid = tid >> 5;
    int b = blockIdx.y;
    int z = blockIdx.z;               // kv split 0..3
    int qrow0 = b * TT + blockIdx.x * 128;
    int kbase = b * TT + z * (NKT_SPLIT * 64);
    int wq0 = wid * 32;

    // load Q tile (hi/lo, swizzled): 128 rows x 2 planes
    {
        int r = tid;
        const uint4* shi = (const uint4*)(g_Qhi + (size_t)(qrow0 + r) * AA);
        const uint4* slo = (const uint4*)(g_Qlo + (size_t)(qrow0 + r) * AA);
        #pragma unroll
        for (int j = 0; j < 8; j++) {
            *(uint4*)(sm + tadr(AT_QHI, r, j*16)) = shi[j];
            *(uint4*)(sm + tadr(AT_QLO, r, j*16)) = slo[j];
        }
    }

    // prime K tile 0 + wz
    {
        int krow0 = kbase;
        int r = tid & 63;
        const char* src = (tid < 64)
            ? (const char*)(g_Khi + (size_t)(krow0 + r) * AA)
            : (const char*)(g_Klo + (size_t)(krow0 + r) * AA);
        uint32_t base = smb + AT_K + ((tid < 64) ? 0 : 8192);
        #pragma unroll
        for (int j = 0; j < 8; j++) CPA(tadr(base, r, j*16), src + j*16);
        if (tid < 32) CPA(smb + AT_WS + tid*16, (const char*)(g_wz + krow0) + tid*16);
        CPC();
    }
    CPW0();
    __syncthreads();

    // hoist Q fragments to registers (loop-invariant): 64 regs
    uint32_t qhi[4][2][4], qlo[4][2][4];
    #pragma unroll
    for (int ks = 0; ks < 4; ks++) {
        int akb = ks*32 + ((lane >> 4) << 4);
        #pragma unroll
        for (int mf = 0; mf < 2; mf++) {
            int arw = wq0 + mf*16 + (lane & 15);
            ldsm4(qhi[ks][mf], tadr(smb + AT_QHI, arw, akb));
            ldsm4(qlo[ks][mf], tadr(smb + AT_QLO, arw, akb));
        }
    }

    const float KZ2 = 1.4426950408889634e-8f; // 1e-8 * log2(e)
    float l[4], acc[4];
    #pragma unroll
    for (int h = 0; h < 4; h++) { l[h] = 0.f; acc[h] = 0.f; }

    for (int kt = 0; kt < NKT_SPLIT; kt++) {
        int buf = kt & 1;
        if (kt + 1 < NKT_SPLIT) {
            int krow0 = kbase + (kt + 1) * 64;
            int r = tid & 63;
            const char* src = (tid < 64)
                ? (const char*)(g_Khi + (size_t)(krow0 + r) * AA)
                : (const char*)(g_Klo + (size_t)(krow0 + r) * AA);
            uint32_t base = smb + AT_K + (buf ^ 1) * 16384 + ((tid < 64) ? 0 : 8192);
            #pragma unroll
            for (int j = 0; j < 8; j++) CPA(tadr(base, r, j*16), src + j*16);
            if (tid < 32) CPA(smb + AT_WS + (buf ^ 1) * 512 + tid*16,
                              (const char*)(g_wz + krow0) + tid*16);
            CPC();
        }

        uint32_t khi = smb + AT_K + buf * 16384;
        uint32_t klo = khi + 8192;
        const float2* wkp = (const float2*)(sm + AT_WS + buf * 512);
        int brow = (lane & 7) | ((lane >> 4) << 3);

        #pragma unroll
        for (int nfp = 0; nfp < 4; nfp++) {
            // 3 independent accumulator groups: chain depth 4 each
            float C1[2][2][4], C2[2][2][4], C3[2][2][4];
            #pragma unroll
            for (int mf = 0; mf < 2; mf++)
                #pragma unroll
                for (int nh = 0; nh < 2; nh++)
                    #pragma unroll
                    for (int c = 0; c < 4; c++) {
                        C1[mf][nh][c] = 0.f; C2[mf][nh][c] = 0.f; C3[mf][nh][c] = 0.f;
                    }

            #pragma unroll
            for (int ks = 0; ks < 4; ks++) {
                int bkb = ks*32 + ((lane & 8) << 1);
                uint32_t bhi[4], blo[4];
                ldsm4(bhi, tadr(khi, nfp*16 + brow, bkb));
                ldsm4(blo, tadr(klo, nfp*16 + brow, bkb));
                #pragma unroll
                for (int mf = 0; mf < 2; mf++) {
                    // interleaved: consecutive MMAs hit different accumulators
                    mma16816(C1[mf][0], qhi[ks][mf], &bhi[0]);
                    mma16816(C2[mf][0], qhi[ks][mf], &blo[0]);
                    mma16816(C3[mf][0], qlo[ks][mf], &bhi[0]);
                    mma16816(C1[mf][1], qhi[ks][mf], &bhi[2]);
                    mma16816(C2[mf][1], qhi[ks][mf], &blo[2]);
                    mma16816(C3[mf][1], qlo[ks][mf], &bhi[2]);
                }
            }

            // softmax for this nfp group's 16 columns (sum the 3 groups here)
            #pragma unroll
            for (int nh = 0; nh < 2; nh++) {
                #pragma unroll
                for (int j2 = 0; j2 < 2; j2++) {
                    int col = nfp*16 + nh*8 + (lane & 3)*2 + j2;
                    float2 wk = wkp[col];
                    #pragma unroll
                    for (int mf = 0; mf < 2; mf++)
                        #pragma unroll
                        for (int h = 0; h < 2; h++) {
                            int ci = (h << 1) + j2;
                            float raw = C1[mf][nh][ci] + C2[mf][nh][ci] + C3[mf][nh][ci];
                            float v = (wk.y != 0.f) ? KZ2 : raw;
                            float p = ex2f(v);
                            l[mf*2 + h] += p;
                            acc[mf*2 + h] += p * wk.x;
                        }
                }
            }
        }

        if (kt + 1 < NKT_SPLIT) CPW0();
        __syncthreads();
    }

    #pragma unroll
    for (int mf = 0; mf < 2; mf++)
        #pragma unroll
        for (int h = 0; h < 2; h++) {
            float lv = l[mf*2 + h], av = acc[mf*2 + h];
            lv += __shfl_xor_sync(0xffffffffu, lv, 1);
            lv += __shfl_xor_sync(0xffffffffu, lv, 2);
            av += __shfl_xor_sync(0xffffffffu, av, 1);
            av += __shfl_xor_sync(0xffffffffu, av, 2);
            if ((lane & 3) == 0) {
                int row = qrow0 + wq0 + mf*16 + h*8 + (lane >> 2);
                atomicAdd(&g_l[row], lv);
                atomicAdd(&g_acc[row], av);
            }
        }
}

// ---------------- kernel 3: out[b,d] += sum_t inp[b,t,d] * (acc[t]/l[t]) ----------------
__global__ __launch_bounds__(128) void k_out2(const float* __restrict__ inp,
                                              float* __restrict__ out) {
    __shared__ float c_sm[64];
    int b = blockIdx.y;
    int ts = blockIdx.x;            // t-split 0..31
    int td = threadIdx.x;           // float4 column 0..127
    if (td < 64) {
        int idx = b * TT + ts * 64 + td;
        c_sm[td] = g_acc[idx] / g_l[idx];
    }
    __syncthreads();
    const float4* ip = (const float4*)(inp + (size_t)b * TT * DD) + (size_t)(ts * 64) * 128 + td;
    float4 acc = make_float4(0.f, 0.f, 0.f, 0.f);
    #pragma unroll 8
    for (int t = 0; t < 64; t++) {
        float4 x = ip[(size_t)t * 128];
        float cv = c_sm[t];
        acc.x += x.x * cv; acc.y += x.y * cv;
        acc.z += x.z * cv; acc.w += x.w * cv;
    }
    float* op = out + b * DD + td * 4;
    atomicAdd(op + 0, acc.x);
    atomicAdd(op + 1, acc.y);
    atomicAdd(op + 2, acc.z);
    atomicAdd(op + 3, acc.w);
}

// ---------------- launch ----------------
extern "C" void kernel_launch(void* const* d_in, const int* in_sizes, int n_in,
                              void* d_out, int out_size) {
    const float* inp = (const float*)d_in[0];
    const float* Wq  = (const float*)d_in[1];
    const float* bq  = (const float*)d_in[2];
    const float* Wk  = (const float*)d_in[3];
    const float* bk  = (const float*)d_in[4];
    const float* Wv  = (const float*)d_in[5];
    const float* bv  = (const float*)d_in[6];
    float* out = (float*)d_out;

    static int inited = 0;
    if (!inited) {
        cudaFuncSetAttribute(k_proj_mma, cudaFuncAttributeMaxDynamicSharedMemorySize, PJ_SMEM);
        cudaFuncSetAttribute(k_attn_mma, cudaFuncAttributeMaxDynamicSharedMemorySize, AT_SMEM);
        inited = 1;
    }

    k_zero<<<64, 512>>>(out);                                  // launch 1
    k_wsum<<<64, 256>>>(Wq, Wk, Wv, bq, bk, bv);               // launch 2
    k_proj_mma<<<NROWS / 64, 256, PJ_SMEM>>>(inp, bq, bk);     // launch 3
    k_attn_mma<<<dim3(TT / 128, BB, 4), 128, AT_SMEM>>>();     // launch 4 (profiled)
    k_out2<<<dim3(32, BB), 128>>>(inp, out);                   // launch 5
}

// round 13
// speedup vs baseline: 1.1518x; 1.1518x over previous
#include <cuda_runtime.h>
#include <cuda_bf16.h>
#include <cstdint>

#define BB 16
#define TT 2048
#define DD 512
#define AA 64
#define NROWS (BB*TT)

// ---------------- device scratch ----------------
__device__ __align__(16) float g_Qf[NROWS*AA];   // fp32, pre-scaled by 0.125*log2e
__device__ __align__(16) float g_Kf[NROWS*AA];   // fp32
__device__ __align__(16) __nv_bfloat16 g_WThi[128*DD];  // [n][k], n: 0..63 Q, 64..127 K
__device__ __align__(16) __nv_bfloat16 g_WTlo[128*DD];
__device__ __align__(16) float2 g_wz[NROWS];  // (q_mask*vsum, kz) per key row
__device__ __align__(16) float g_l[NROWS];    // softmax denominator partials
__device__ __align__(16) float g_acc[NROWS];  // softmax numerator partials
__device__ float g_wqs[DD], g_wks[DD], g_wvs[DD];
__device__ float g_bs[3];

#define SC2F 0.18033688011112043f   // 0.125 * log2(e)

// ---------------- helpers ----------------
__device__ __forceinline__ uint32_t smem_u32(const void* p) {
    return (uint32_t)__cvta_generic_to_shared(p);
}
__device__ __forceinline__ float ex2f(float x) {
    float y; asm("ex2.approx.ftz.f32 %0, %1;" : "=f"(y) : "f"(x)); return y;
}
__device__ __forceinline__ uint32_t cvt_tf32(float f) {
    uint32_t u; asm("cvt.rna.tf32.f32 %0, %1;" : "=r"(u) : "f"(f)); return u;
}
__device__ __forceinline__ void ldsm4(uint32_t* r, uint32_t addr) {
    asm volatile("ldmatrix.sync.aligned.m8n8.x4.shared.b16 {%0,%1,%2,%3}, [%4];"
        : "=r"(r[0]), "=r"(r[1]), "=r"(r[2]), "=r"(r[3]) : "r"(addr));
}
__device__ __forceinline__ void mma16816(float* c, const uint32_t* a, const uint32_t* b) {
    asm volatile("mma.sync.aligned.m16n8k16.row.col.f32.bf16.bf16.f32 "
        "{%0,%1,%2,%3}, {%4,%5,%6,%7}, {%8,%9}, {%0,%1,%2,%3};"
        : "+f"(c[0]), "+f"(c[1]), "+f"(c[2]), "+f"(c[3])
        : "r"(a[0]), "r"(a[1]), "r"(a[2]), "r"(a[3]), "r"(b[0]), "r"(b[1]));
}
__device__ __forceinline__ void mma168tf(float* c, const uint32_t* a, uint32_t b0, uint32_t b1) {
    asm volatile("mma.sync.aligned.m16n8k8.row.col.f32.tf32.tf32.f32 "
        "{%0,%1,%2,%3}, {%4,%5,%6,%7}, {%8,%9}, {%0,%1,%2,%3};"
        : "+f"(c[0]), "+f"(c[1]), "+f"(c[2]), "+f"(c[3])
        : "r"(a[0]), "r"(a[1]), "r"(a[2]), "r"(a[3]), "r"(b0), "r"(b1));
}
#define CPA(dst, src) asm volatile("cp.async.cg.shared.global [%0], [%1], 16;" :: "r"(dst), "l"(src))
#define CPC() asm volatile("cp.async.commit_group;" ::: "memory")
#define CPW0() asm volatile("cp.async.wait_group 0;" ::: "memory")
#define CPW1() asm volatile("cp.async.wait_group 1;" ::: "memory")

// 128-byte rows, xor swizzle (bits 4-6) for conflict-free ldmatrix (proj only)
__device__ __forceinline__ uint32_t tadr(uint32_t base, int r, int kb) {
    return base + ((((uint32_t)r << 7) | (uint32_t)kb) ^ (((uint32_t)(r & 7)) << 4));
}
__device__ __forceinline__ uint32_t pk2(__nv_bfloat16 a, __nv_bfloat16 b) {
    __nv_bfloat162 t = __halves2bfloat162(a, b);
    return *reinterpret_cast<uint32_t*>(&t);
}
__device__ __forceinline__ uint32_t pkf(float a, float b) {
    __nv_bfloat162 t = __floats2bfloat162_rn(a, b);
    return *reinterpret_cast<uint32_t*>(&t);
}

// ---------------- kernel A: zero out + l/acc partials ----------------
__global__ __launch_bounds__(512) void k_zero(float* __restrict__ out) {
    int idx = blockIdx.x * 512 + threadIdx.x;
    g_l[idx] = 0.f;
    g_acc[idx] = 0.f;
    if (blockIdx.x < 16) out[blockIdx.x * 512 + threadIdx.x] = 0.f;
}

// ---------------- kernel 0: W col sums + transpose, parallel (warp per d) ----------------
__global__ __launch_bounds__(256) void k_wsum(const float* __restrict__ Wq, const float* __restrict__ Wk,
                       const float* __restrict__ Wv,
                       const float* __restrict__ bq, const float* __restrict__ bk,
                       const float* __restrict__ bv) {
    int wid = threadIdx.x >> 5, lane = threadIdx.x & 31;
    int d = blockIdx.x * 8 + wid;

    float wq0 = Wq[d*AA + lane],      wq1 = Wq[d*AA + 32 + lane];
    float wk0 = Wk[d*AA + lane],      wk1 = Wk[d*AA + 32 + lane];
    float wv0 = Wv[d*AA + lane],      wv1 = Wv[d*AA + 32 + lane];

    float sq = wq0 + wq1, sk = wk0 + wk1, sv = wv0 + wv1;
    #pragma unroll
    for (int off = 16; off > 0; off >>= 1) {
        sq += __shfl_xor_sync(0xffffffffu, sq, off);
        sk += __shfl_xor_sync(0xffffffffu, sk, off);
        sv += __shfl_xor_sync(0xffffffffu, sv, off);
    }
    if (lane == 0) { g_wqs[d] = sq; g_wks[d] = sk; g_wvs[d] = sv; }

    #pragma unroll
    for (int half = 0; half < 2; half++) {
        int a = lane + half * 32;
        float vq = half ? wq1 : wq0;
        float vk = half ? wk1 : wk0;
        __nv_bfloat16 hq = __float2bfloat16_rn(vq);
        __nv_bfloat16 hk = __float2bfloat16_rn(vk);
        g_WThi[a*DD + d]        = hq;
        g_WTlo[a*DD + d]        = __float2bfloat16_rn(vq - __bfloat162float(hq));
        g_WThi[(64 + a)*DD + d] = hk;
        g_WTlo[(64 + a)*DD + d] = __float2bfloat16_rn(vk - __bfloat162float(hk));
    }

    if (blockIdx.x == 0 && threadIdx.x < 3) {
        const float* bb = (threadIdx.x == 0) ? bq : (threadIdx.x == 1) ? bk : bv;
        float s = 0.f;
        #pragma unroll 8
        for (int a = 0; a < AA; a++) s += bb[a];
        g_bs[threadIdx.x] = s;
    }
}

// ---------------- kernel 1: HMMA Q,K projection (split bf16, full precision) ----------------
#define PJ_A 0                    // 2 bufs x 8K (64 rows x 128B)
#define PJ_B 16384                // 2 bufs x 16K (128 n x 128B)
#define PJ_SMEM (16384 + 32768)

__global__ __launch_bounds__(256) void k_proj_mma(const float* __restrict__ inp,
                                                  const float* __restrict__ bq,
                                                  const float* __restrict__ bk) {
    extern __shared__ char sm[];
    uint32_t smb = smem_u32(sm);
    int tid = threadIdx.x;
    int lane = tid & 31;
    int wid = tid >> 5;
    int m0 = (wid >> 2) * 32;
    int wn = wid & 3;
    int n0 = wn * 32;
    int rowbase = blockIdx.x * 64;

    int ar = tid >> 2, aq = tid & 3;
    int bn = tid >> 1, bh = tid & 1;

    float C[2][4][4];
    #pragma unroll
    for (int a = 0; a < 2; a++)
        #pragma unroll
        for (int b = 0; b < 4; b++)
            #pragma unroll
            for (int c = 0; c < 4; c++) C[a][b][c] = 0.f;
    float dq = 0.f, dk = 0.f, dv = 0.f;

    const float* arow_p = inp + (size_t)(rowbase + ar) * DD + aq * 8;
    const char* bsrc_h = (const char*)g_WThi + (size_t)bn * 1024 + bh * 32;
    const char* bsrc_l = (const char*)g_WTlo + (size_t)bn * 1024 + bh * 32;

    float4 xa = *(const float4*)(arow_p);
    float4 xb = *(const float4*)(arow_p + 4);
    {
        uint32_t bb = smb + PJ_B;
        CPA(tadr(bb, bn, bh*32),           bsrc_h);
        CPA(tadr(bb, bn, bh*32 + 16),      bsrc_h + 16);
        CPA(tadr(bb, bn, 64 + bh*32),      bsrc_l);
        CPA(tadr(bb, bn, 64 + bh*32 + 16), bsrc_l + 16);
        CPC();
    }

    for (int kc = 0; kc < 16; kc++) {
        int buf = kc & 1;
        {
            int koff = kc * 32 + aq * 8;
            const float4* wq4 = (const float4*)(g_wqs + koff);
            const float4* wk4 = (const float4*)(g_wks + koff);
            const float4* wv4 = (const float4*)(g_wvs + koff);
            float4 a0 = wq4[0], a1 = wq4[1];
            dq += xa.x*a0.x + xa.y*a0.y + xa.z*a0.z + xa.w*a0.w
                + xb.x*a1.x + xb.y*a1.y + xb.z*a1.z + xb.w*a1.w;
            float4 b0 = wk4[0], b1 = wk4[1];
            dk += xa.x*b0.x + xa.y*b0.y + xa.z*b0.z + xa.w*b0.w
                + xb.x*b1.x + xb.y*b1.y + xb.z*b1.z + xb.w*b1.w;
            float4 c0 = wv4[0], c1 = wv4[1];
            dv += xa.x*c0.x + xa.y*c0.y + xa.z*c0.z + xa.w*c0.w
                + xb.x*c1.x + xb.y*c1.y + xb.z*c1.z + xb.w*c1.w;
        }
        {
            __nv_bfloat16 h0 = __float2bfloat16_rn(xa.x), h1 = __float2bfloat16_rn(xa.y);
            __nv_bfloat16 h2 = __float2bfloat16_rn(xa.z), h3 = __float2bfloat16_rn(xa.w);
            __nv_bfloat16 h4 = __float2bfloat16_rn(xb.x), h5 = __float2bfloat16_rn(xb.y);
            __nv_bfloat16 h6 = __float2bfloat16_rn(xb.z), h7 = __float2bfloat16_rn(xb.w);
            uint4 hw, lw;
            hw.x = pk2(h0, h1); hw.y = pk2(h2, h3); hw.z = pk2(h4, h5); hw.w = pk2(h6, h7);
            lw.x = pkf(xa.x - __bfloat162float(h0), xa.y - __bfloat162float(h1));
            lw.y = pkf(xa.z - __bfloat162float(h2), xa.w - __bfloat162float(h3));
            lw.z = pkf(xb.x - __bfloat162float(h4), xb.y - __bfloat162float(h5));
            lw.w = pkf(xb.z - __bfloat162float(h6), xb.w - __bfloat162float(h7));
            uint32_t abase = PJ_A + buf * 8192;
            *(uint4*)(sm + tadr(abase, ar, aq*16))      = hw;
            *(uint4*)(sm + tadr(abase, ar, 64 + aq*16)) = lw;
        }
        if (kc < 15) {
            xa = *(const float4*)(arow_p + (kc + 1) * 32);
            xb = *(const float4*)(arow_p + (kc + 1) * 32 + 4);
        }
        if (kc < 15) {
            uint32_t bb = smb + PJ_B + (buf ^ 1) * 16384;
            const char* bh_p = bsrc_h + (kc + 1) * 64;
            const char* bl_p = bsrc_l + (kc + 1) * 64;
            CPA(tadr(bb, bn, bh*32),           bh_p);
            CPA(tadr(bb, bn, bh*32 + 16),      bh_p + 16);
            CPA(tadr(bb, bn, 64 + bh*32),      bl_p);
            CPA(tadr(bb, bn, 64 + bh*32 + 16), bl_p + 16);
            CPC();
            CPW1();
        } else {
            CPW0();
        }
        __syncthreads();

        uint32_t Ab = smb + PJ_A + buf * 8192;
        uint32_t Bb = smb + PJ_B + buf * 16384;
        #pragma unroll
        for (int ks = 0; ks < 2; ks++) {
            int akb = ks*32 + ((lane >> 4) << 4);
            int arw = m0 + (lane & 15);
            uint32_t ahi[2][4], alo[2][4];
            ldsm4(ahi[0], tadr(Ab, arw,      akb));
            ldsm4(ahi[1], tadr(Ab, arw + 16, akb));
            ldsm4(alo[0], tadr(Ab, arw,      akb + 64));
            ldsm4(alo[1], tadr(Ab, arw + 16, akb + 64));
            int brow = (lane & 7) | ((lane >> 4) << 3);
            int bkb = ks*32 + ((lane & 8) << 1);
            uint32_t bhi[4][2], blo[4][2];
            ldsm4(&bhi[0][0], tadr(Bb, n0 + brow,      bkb));
            ldsm4(&bhi[2][0], tadr(Bb, n0 + 16 + brow, bkb));
            ldsm4(&blo[0][0], tadr(Bb, n0 + brow,      bkb + 64));
            ldsm4(&blo[2][0], tadr(Bb, n0 + 16 + brow, bkb + 64));
            #pragma unroll
            for (int mf = 0; mf < 2; mf++)
                #pragma unroll
                for (int nf = 0; nf < 4; nf++) {
                    mma16816(C[mf][nf], ahi[mf], bhi[nf]);
                    mma16816(C[mf][nf], ahi[mf], blo[nf]);
                    mma16816(C[mf][nf], alo[mf], bhi[nf]);
                }
        }
    }

    // ---- finalize mask rowsums ----
    dq += __shfl_xor_sync(0xffffffffu, dq, 1);
    dq += __shfl_xor_sync(0xffffffffu, dq, 2);
    dk += __shfl_xor_sync(0xffffffffu, dk, 1);
    dk += __shfl_xor_sync(0xffffffffu, dk, 2);
    dv += __shfl_xor_sync(0xffffffffu, dv, 1);
    dv += __shfl_xor_sync(0xffffffffu, dv, 2);
    if (aq == 0) {
        float qs = dq + g_bs[0];
        float ks_ = dk + g_bs[1];
        float vs = dv + g_bs[2];
        g_wz[rowbase + ar] = make_float2((qs != 0.f) ? vs : 0.f,
                                         (ks_ == 0.f) ? 1.f : 0.f);
    }

    // ---- epilogue: bias, Q pre-scaled, fp32 store ----
    float* dst; const float* bias; int nb; float scl;
    if (wn < 2) { dst = g_Qf; bias = bq; nb = wn * 32; scl = SC2F; }
    else        { dst = g_Kf; bias = bk; nb = (wn - 2) * 32; scl = 1.0f; }
    #pragma unroll
    for (int mf = 0; mf < 2; mf++) {
        int r0 = rowbase + m0 + mf*16 + (lane >> 2);
        #pragma unroll
        for (int nf = 0; nf < 4; nf++) {
            int c = nb + nf*8 + (lane & 3)*2;
            float b0 = __ldg(bias + c), b1 = __ldg(bias + c + 1);
            float2 v01 = make_float2((C[mf][nf][0] + b0) * scl, (C[mf][nf][1] + b1) * scl);
            float2 v23 = make_float2((C[mf][nf][2] + b0) * scl, (C[mf][nf][3] + b1) * scl);
            *(float2*)(dst + (size_t)r0*AA + c)     = v01;
            *(float2*)(dst + (size_t)(r0+8)*AA + c) = v23;
        }
    }
}

// ---------------- kernel 2: tf32 flash attention ----------------
// grid (16 q-tiles, BB, 4 kv-splits); CTA 128 thr; 128q/CTA, 32q/warp; 8 key tiles of 64.
// m16n8k8 tf32: 4.2M MMAs total. K tiles fp32 in smem, rows padded to 272B (conflict-free).
#define AT_KROW 272                // 68 floats per row
#define AT_KBUF (64 * AT_KROW)     // 17408 B
#define AT_K    0                  // 2 bufs
#define AT_WS   (2 * AT_KBUF)      // 2 x 512B
#define AT_SMEM (2 * AT_KBUF + 1024)
#define NKT_SPLIT 8

__global__ __launch_bounds__(128, 4) void k_attn_mma() {
    extern __shared__ char sm[];
    uint32_t smb = smem_u32(sm);
    int tid = threadIdx.x;
    int lane = tid & 31;
    int wid = tid >> 5;
    int tig = lane & 3, g = lane >> 2;
    int b = blockIdx.y;
    int z = blockIdx.z;
    int qrow0 = b * TT + blockIdx.x * 128;
    int kbase = b * TT + z * (NKT_SPLIT * 64);
    int wq0 = wid * 32;

    // prime K tile 0 + wz: 64 rows x 256B data (rows padded to 272B in smem)
    {
        int r = tid >> 1, half = tid & 1;
        const char* src = (const char*)(g_Kf + (size_t)(kbase + r) * AA) + half * 128;
        uint32_t base = smb + AT_K + r * AT_KROW + half * 128;
        #pragma unroll
        for (int j = 0; j < 8; j++) CPA(base + j*16, src + j*16);
        if (tid < 32) CPA(smb + AT_WS + tid*16, (const char*)(g_wz + kbase) + tid*16);
        CPC();
    }

    // hoist Q fragments from global (loop-invariant): 64 regs, cvt.rna to tf32
    uint32_t qf[8][2][4];
    #pragma unroll
    for (int ks = 0; ks < 8; ks++) {
        int col = ks*8 + tig;
        #pragma unroll
        for (int mf = 0; mf < 2; mf++) {
            int row = qrow0 + wq0 + mf*16 + g;
            qf[ks][mf][0] = cvt_tf32(__ldg(g_Qf + (size_t)row*AA + col));
            qf[ks][mf][1] = cvt_tf32(__ldg(g_Qf + (size_t)(row+8)*AA + col));
            qf[ks][mf][2] = cvt_tf32(__ldg(g_Qf + (size_t)row*AA + col + 4));
            qf[ks][mf][3] = cvt_tf32(__ldg(g_Qf + (size_t)(row+8)*AA + col + 4));
        }
    }

    CPW0();
    __syncthreads();

    const float KZ2 = 1.4426950408889634e-8f; // 1e-8 * log2(e)
    float l[4], acc[4];
    #pragma unroll
    for (int h = 0; h < 4; h++) { l[h] = 0.f; acc[h] = 0.f; }

    for (int kt = 0; kt < NKT_SPLIT; kt++) {
        int buf = kt & 1;
        if (kt + 1 < NKT_SPLIT) {
            int krow0 = kbase + (kt + 1) * 64;
            int r = tid >> 1, half = tid & 1;
            const char* src = (const char*)(g_Kf + (size_t)(krow0 + r) * AA) + half * 128;
            uint32_t base = smb + AT_K + (buf ^ 1) * AT_KBUF + r * AT_KROW + half * 128;
            #pragma unroll
            for (int j = 0; j < 8; j++) CPA(base + j*16, src + j*16);
            if (tid < 32) CPA(smb + AT_WS + (buf ^ 1) * 512 + tid*16,
                              (const char*)(g_wz + krow0) + tid*16);
            CPC();
        }

        const char* kb = sm + AT_K + buf * AT_KBUF;
        const float2* wkp = (const float2*)(sm + AT_WS + buf * 512);

        #pragma unroll
        for (int nt = 0; nt < 8; nt++) {
            float C[2][4];
            #pragma unroll
            for (int mf = 0; mf < 2; mf++)
                #pragma unroll
                for (int c = 0; c < 4; c++) C[mf][c] = 0.f;

            const char* bp = kb + (nt*8 + g) * AT_KROW + tig * 4;
            #pragma unroll
            for (int ks = 0; ks < 8; ks++) {
                uint32_t b0 = *(const uint32_t*)(bp + ks*32);
                uint32_t b1 = *(const uint32_t*)(bp + ks*32 + 16);
                mma168tf(C[0], qf[ks][0], b0, b1);
                mma168tf(C[1], qf[ks][1], b0, b1);
            }

            // softmax for this nt group's 8 key columns
            #pragma unroll
            for (int j2 = 0; j2 < 2; j2++) {
                int col = nt*8 + tig*2 + j2;
                float2 wk = wkp[col];
                #pragma unroll
                for (int mf = 0; mf < 2; mf++)
                    #pragma unroll
                    for (int h = 0; h < 2; h++) {
                        float raw = C[mf][(h << 1) + j2];
                        float v = (wk.y != 0.f) ? KZ2 : raw;
                        float p = ex2f(v);
                        l[mf*2 + h] += p;
                        acc[mf*2 + h] += p * wk.x;
                    }
            }
        }

        if (kt + 1 < NKT_SPLIT) CPW0();
        __syncthreads();
    }

    #pragma unroll
    for (int mf = 0; mf < 2; mf++)
        #pragma unroll
        for (int h = 0; h < 2; h++) {
            float lv = l[mf*2 + h], av = acc[mf*2 + h];
            lv += __shfl_xor_sync(0xffffffffu, lv, 1);
            lv += __shfl_xor_sync(0xffffffffu, lv, 2);
            av += __shfl_xor_sync(0xffffffffu, av, 1);
            av += __shfl_xor_sync(0xffffffffu, av, 2);
            if ((lane & 3) == 0) {
                int row = qrow0 + wq0 + mf*16 + h*8 + (lane >> 2);
                atomicAdd(&g_l[row], lv);
                atomicAdd(&g_acc[row], av);
            }
        }
}

// ---------------- kernel 3: out[b,d] += sum_t inp[b,t,d] * (acc[t]/l[t]) ----------------
__global__ __launch_bounds__(128) void k_out2(const float* __restrict__ inp,
                                              float* __restrict__ out) {
    __shared__ float c_sm[64];
    int b = blockIdx.y;
    int ts = blockIdx.x;
    int td = threadIdx.x;
    if (td < 64) {
        int idx = b * TT + ts * 64 + td;
        c_sm[td] = g_acc[idx] / g_l[idx];
    }
    __syncthreads();
    const float4* ip = (const float4*)(inp + (size_t)b * TT * DD) + (size_t)(ts * 64) * 128 + td;
    float4 acc = make_float4(0.f, 0.f, 0.f, 0.f);
    #pragma unroll 8
    for (int t = 0; t < 64; t++) {
        float4 x = ip[(size_t)t * 128];
        float cv = c_sm[t];
        acc.x += x.x * cv; acc.y += x.y * cv;
        acc.z += x.z * cv; acc.w += x.w * cv;
    }
    float* op = out + b * DD + td * 4;
    atomicAdd(op + 0, acc.x);
    atomicAdd(op + 1, acc.y);
    atomicAdd(op + 2, acc.z);
    atomicAdd(op + 3, acc.w);
}

// ---------------- launch ----------------
extern "C" void kernel_launch(void* const* d_in, const int* in_sizes, int n_in,
                              void* d_out, int out_size) {
    const float* inp = (const float*)d_in[0];
    const float* Wq  = (const float*)d_in[1];
    const float* bq  = (const float*)d_in[2];
    const float* Wk  = (const float*)d_in[3];
    const float* bk  = (const float*)d_in[4];
    const float* Wv  = (const float*)d_in[5];
    const float* bv  = (const float*)d_in[6];
    float* out = (float*)d_out;

    static int inited = 0;
    if (!inited) {
        cudaFuncSetAttribute(k_proj_mma, cudaFuncAttributeMaxDynamicSharedMemorySize, PJ_SMEM);
        cudaFuncSetAttribute(k_attn_mma, cudaFuncAttributeMaxDynamicSharedMemorySize, AT_SMEM);
        inited = 1;
    }

    k_zero<<<64, 512>>>(out);                                  // launch 1
    k_wsum<<<64, 256>>>(Wq, Wk, Wv, bq, bk, bv);               // launch 2
    k_proj_mma<<<NROWS / 64, 256, PJ_SMEM>>>(inp, bq, bk);     // launch 3
    k_attn_mma<<<dim3(TT / 128, BB, 4), 128, AT_SMEM>>>();     // launch 4 (profiled)
    k_out2<<<dim3(32, BB), 128>>>(inp, out);                   // launch 5
}